// round 1
// baseline (speedup 1.0000x reference)
#include <cuda_runtime.h>
#include <cstdint>
#include <math.h>

#define T_LEN  2048
#define D_EMB  300
#define H_DIM  256
#define G4     1024
#define K_TAGS 48
#define START_TAG 46
#define STOP_TAG  47

// ---------------- scratch (device globals; no allocation) ----------------
__device__ float g_x[T_LEN * D_EMB];        // gathered embeddings [T, D]
__device__ float g_xg[2][T_LEN * G4];       // input projections per dir [T, 4H]
__device__ float g_hs[2][T_LEN * H_DIM];    // hidden states per dir, time-aligned
__device__ float g_feats[T_LEN * K_TAGS];   // emission features [T, K]

// ---------------- 1) embedding gather ----------------
__global__ void gather_kernel(const int* __restrict__ sent,
                              const float* __restrict__ E) {
    int idx = blockIdx.x * blockDim.x + threadIdx.x;
    int total = T_LEN * D_EMB;
    for (; idx < total; idx += gridDim.x * blockDim.x) {
        int t = idx / D_EMB;
        int d = idx - t * D_EMB;
        long long row = sent[t];
        g_x[idx] = E[row * D_EMB + d];
    }
}

// ---------------- 2) xg GEMM: [T,D] @ [4H,D]^T + (b_ih + b_hh) ----------------
#define BM 64
#define BN 64
#define BK 8
__global__ void xg_gemm_kernel(const float* __restrict__ Wf,
                               const float* __restrict__ Wb,
                               const float* __restrict__ bihf,
                               const float* __restrict__ bhhf,
                               const float* __restrict__ bihb,
                               const float* __restrict__ bhhb) {
    int dir = blockIdx.z;
    const float* W  = dir ? Wb   : Wf;
    const float* b1 = dir ? bihb : bihf;
    const float* b2 = dir ? bhhb : bhhf;

    __shared__ float As[BK][BM];
    __shared__ float Bs[BK][BN];

    int t0 = blockIdx.x * BM;
    int r0 = blockIdx.y * BN;
    int tid = threadIdx.x;           // 256 threads
    int tx = tid & 15;
    int ty = tid >> 4;

    float acc[4][4];
#pragma unroll
    for (int i = 0; i < 4; i++)
#pragma unroll
        for (int j = 0; j < 4; j++) acc[i][j] = 0.f;

    for (int k0 = 0; k0 < D_EMB; k0 += BK) {
#pragma unroll
        for (int l = 0; l < 2; l++) {
            int idx = tid + l * 256;       // 0..511
            int row = idx >> 3;            // 0..63
            int kk  = idx & 7;
            int kglob = k0 + kk;
            // A tile (gathered embeddings, reversed time for backward dir)
            int tg = t0 + row;
            int ts = dir ? (T_LEN - 1 - tg) : tg;
            float va = 0.f, vb = 0.f;
            if (kglob < D_EMB) {
                va = g_x[ts * D_EMB + kglob];
                vb = W[(r0 + row) * D_EMB + kglob];
            }
            As[kk][row] = va;
            Bs[kk][row] = vb;
        }
        __syncthreads();
#pragma unroll
        for (int kk = 0; kk < BK; kk++) {
            float ra[4], rb[4];
#pragma unroll
            for (int i = 0; i < 4; i++) ra[i] = As[kk][ty * 4 + i];
#pragma unroll
            for (int j = 0; j < 4; j++) rb[j] = Bs[kk][tx * 4 + j];
#pragma unroll
            for (int i = 0; i < 4; i++)
#pragma unroll
                for (int j = 0; j < 4; j++) acc[i][j] += ra[i] * rb[j];
        }
        __syncthreads();
    }

#pragma unroll
    for (int i = 0; i < 4; i++) {
        int t = t0 + ty * 4 + i;
#pragma unroll
        for (int j = 0; j < 4; j++) {
            int r = r0 + tx * 4 + j;
            g_xg[dir][t * G4 + r] = acc[i][j] + b1[r] + b2[r];
        }
    }
}

// ---------------- 3) LSTM recurrence: 8-CTA cluster per direction ----------------
// Cluster of 8 CTAs; CTA `rank` owns hidden slice [rank*32, rank*32+32).
// Each CTA holds its 128x256 W_hh slice (rows = 4 gates x 32 hidden) in registers:
// warp w (g = w/4, sub = w%4) owns 8 rows (hidden local sub*8..+8), lane l owns
// k-chunk [l*8, l*8+8). h is exchanged via DSMEM each step; one cluster barrier/step.
__global__ void __launch_bounds__(512, 1) __cluster_dims__(8, 1, 1)
lstm_kernel(const float* __restrict__ Whf, const float* __restrict__ Whb) {
    __shared__ float h_buf[2][H_DIM];
    __shared__ float gate_s[128];

    int dir = blockIdx.y;
    const float* Whh = dir ? Whb : Whf;
    const float* xg = g_xg[dir];
    float* hs = g_hs[dir];

    uint32_t rank;
    asm("mov.u32 %0, %%cluster_ctarank;" : "=r"(rank));

    int tid = threadIdx.x;
    int w = tid >> 5;
    int l = tid & 31;
    int g = w >> 2;
    int sub = w & 3;

    // Load W slice into registers
    float wreg[8][8];
    {
        int base_row = g * H_DIM + (int)rank * 32 + sub * 8;
#pragma unroll
        for (int r = 0; r < 8; r++) {
            const float4* p = (const float4*)(Whh + (size_t)(base_row + r) * H_DIM + l * 8);
            float4 a = p[0];
            float4 b = p[1];
            wreg[r][0] = a.x; wreg[r][1] = a.y; wreg[r][2] = a.z; wreg[r][3] = a.w;
            wreg[r][4] = b.x; wreg[r][5] = b.y; wreg[r][6] = b.z; wreg[r][7] = b.w;
        }
    }

    // Zero h buffers
    for (int i = tid; i < 2 * H_DIM; i += 512) ((float*)h_buf)[i] = 0.f;
    float c_reg = 0.f;

    uint32_t hbuf_base = (uint32_t)__cvta_generic_to_shared(&h_buf[0][0]);

    // all CTAs initialized before any DSMEM traffic
    asm volatile("barrier.cluster.arrive.aligned;" ::: "memory");
    asm volatile("barrier.cluster.wait.aligned;" ::: "memory");

    for (int t = 0; t < T_LEN; t++) {
        int cur = t & 1;
        int nxt = cur ^ 1;

        // prefetch xg for this step (consumed ~1000 cyc later, after the barrier)
        float xgv0 = 0.f, xgv1 = 0.f, xgv2 = 0.f, xgv3 = 0.f;
        if (tid < 32) {
            int col = (int)rank * 32 + tid;
            const float* xgt = xg + (size_t)t * G4;
            xgv0 = xgt[col];
            xgv1 = xgt[256 + col];
            xgv2 = xgt[512 + col];
            xgv3 = xgt[768 + col];
        }

        // matvec partials: each lane covers k in [l*8, l*8+8)
        float4 h0 = *(const float4*)&h_buf[cur][l * 8];
        float4 h1 = *(const float4*)&h_buf[cur][l * 8 + 4];
        float hv[8] = {h0.x, h0.y, h0.z, h0.w, h1.x, h1.y, h1.z, h1.w};

        float p[8];
#pragma unroll
        for (int r = 0; r < 8; r++) {
            float acc = 0.f;
#pragma unroll
            for (int j = 0; j < 8; j++) acc += wreg[r][j] * hv[j];
            p[r] = acc;
        }
        // butterfly all-reduce across the warp's 32 k-chunks
#pragma unroll
        for (int off = 16; off > 0; off >>= 1) {
#pragma unroll
            for (int r = 0; r < 8; r++)
                p[r] += __shfl_xor_sync(0xffffffffu, p[r], off);
        }
#pragma unroll
        for (int r = 0; r < 8; r++)
            if (l == r) gate_s[w * 8 + r] = p[r];

        __syncthreads();

        if (tid < 32) {
            float pi = gate_s[tid]       + xgv0;
            float pf = gate_s[32 + tid]  + xgv1;
            float pg = gate_s[64 + tid]  + xgv2;
            float po = gate_s[96 + tid]  + xgv3;
            float iv = 1.f / (1.f + expf(-pi));
            float fv = 1.f / (1.f + expf(-pf));
            float gv = tanhf(pg);
            float ov = 1.f / (1.f + expf(-po));
            c_reg = fv * c_reg + iv * gv;
            float hval = ov * tanhf(c_reg);

            int tout = dir ? (T_LEN - 1 - t) : t;
            hs[(size_t)tout * H_DIM + rank * 32 + tid] = hval;

            // broadcast our h slice into every CTA's next buffer (incl. self)
            uint32_t laddr = hbuf_base + (uint32_t)((nxt * H_DIM + (int)rank * 32 + tid) * 4);
#pragma unroll
            for (int tg = 0; tg < 8; tg++) {
                asm volatile(
                    "{ .reg .b32 ra;\n\t"
                    "mapa.shared::cluster.u32 ra, %0, %1;\n\t"
                    "st.shared::cluster.f32 [ra], %2; }\n\t"
                    :: "r"(laddr), "r"(tg), "f"(hval) : "memory");
            }
        }

        asm volatile("barrier.cluster.arrive.aligned;" ::: "memory");
        asm volatile("barrier.cluster.wait.aligned;" ::: "memory");
    }
}

// ---------------- 4) emission features: feats = [hf|hb] @ W_out^T + b_out ----------------
__global__ void feats_kernel(const float* __restrict__ W_out,
                             const float* __restrict__ b_out) {
    __shared__ float h_s[512];
    int t = blockIdx.x;
    int tid = threadIdx.x;  // 64
    for (int i = tid; i < H_DIM; i += 64) {
        h_s[i]         = g_hs[0][(size_t)t * H_DIM + i];
        h_s[H_DIM + i] = g_hs[1][(size_t)t * H_DIM + i];
    }
    __syncthreads();
    if (tid < K_TAGS) {
        float acc = b_out[tid];
        const float* wr = W_out + (size_t)tid * 512;
#pragma unroll 8
        for (int j = 0; j < 512; j++) acc += h_s[j] * wr[j];
        g_feats[t * K_TAGS + tid] = acc;
    }
}

// ---------------- 5) Viterbi + backtrace (single CTA, bptrs in SMEM) ----------------
#define VIT_SMEM (T_LEN * K_TAGS + 2 * K_TAGS * 4 + 16)
extern __shared__ unsigned char vit_smem[];
__global__ void viterbi_kernel(const float* __restrict__ trans,
                               float* __restrict__ out) {
    unsigned char* bptr = vit_smem;                       // [T][48] u8 = 96KB
    float* fv = (float*)(vit_smem + T_LEN * K_TAGS);      // [2][48]
    int tid = threadIdx.x;  // 64

    float tr[K_TAGS];
    if (tid < K_TAGS) {
#pragma unroll
        for (int j = 0; j < K_TAGS; j++) tr[j] = trans[tid * K_TAGS + j];
        fv[tid] = (tid == START_TAG) ? 0.f : -10000.f;
    }
    __syncthreads();

    for (int t = 0; t < T_LEN; t++) {
        int cur = (t & 1) * K_TAGS;
        int nxt = K_TAGS - cur;
        if (tid < K_TAGS) {
            float feat = g_feats[t * K_TAGS + tid];
            float best = -3.4e38f;
            int arg = 0;
#pragma unroll
            for (int j = 0; j < K_TAGS; j++) {
                float s = fv[cur + j] + tr[j];
                if (s > best) { best = s; arg = j; }   // first-max = jnp.argmax
            }
            fv[nxt + tid] = best + feat;
            bptr[t * K_TAGS + tid] = (unsigned char)arg;
        }
        __syncthreads();
    }

    if (tid == STOP_TAG) {
        int cur = (T_LEN & 1) * K_TAGS;  // = 0 for even T
        float best = -3.4e38f;
        int tag = 0;
#pragma unroll
        for (int j = 0; j < K_TAGS; j++) {
            float s = fv[cur + j] + tr[j];  // tr == transitions[STOP] row
            if (s > best) { best = s; tag = j; }
        }
        out[0] = best;
        for (int t = T_LEN - 1; t >= 0; t--) {
            out[1 + t] = (float)tag;
            tag = bptr[t * K_TAGS + tag];
        }
    }
}

// ---------------- launch ----------------
extern "C" void kernel_launch(void* const* d_in, const int* in_sizes, int n_in,
                              void* d_out, int out_size) {
    const int*   sent   = (const int*)d_in[0];
    const float* E      = (const float*)d_in[1];
    const float* W_ih_f = (const float*)d_in[2];
    const float* W_hh_f = (const float*)d_in[3];
    const float* b_ih_f = (const float*)d_in[4];
    const float* b_hh_f = (const float*)d_in[5];
    const float* W_ih_b = (const float*)d_in[6];
    const float* W_hh_b = (const float*)d_in[7];
    const float* b_ih_b = (const float*)d_in[8];
    const float* b_hh_b = (const float*)d_in[9];
    const float* W_out  = (const float*)d_in[10];
    const float* b_out  = (const float*)d_in[11];
    const float* trans  = (const float*)d_in[12];
    float* out = (float*)d_out;

    cudaFuncSetAttribute(viterbi_kernel,
                         cudaFuncAttributeMaxDynamicSharedMemorySize, VIT_SMEM);

    gather_kernel<<<256, 256>>>(sent, E);

    dim3 ggrid(T_LEN / BM, G4 / BN, 2);
    xg_gemm_kernel<<<ggrid, 256>>>(W_ih_f, W_ih_b, b_ih_f, b_hh_f, b_ih_b, b_hh_b);

    lstm_kernel<<<dim3(8, 2, 1), 512>>>(W_hh_f, W_hh_b);

    feats_kernel<<<T_LEN, 64>>>(W_out, b_out);

    viterbi_kernel<<<1, 64, VIT_SMEM>>>(trans, out);
}